// round 3
// baseline (speedup 1.0000x reference)
#include <cuda_runtime.h>

#define RG 8
#define LC 64
#define NP 4096
#define SD 1024

// ---------------- device scratch ----------------
__device__ float g_centers[RG * LC * SD];
__device__ float g_sums[RG * LC * SD];
__device__ float g_c2[RG * LC];
__device__ float g_x2[RG * NP];
__device__ int   g_counts[RG * LC];
__device__ int   g_labels[RG * NP];
__device__ int   g_init_idx[RG * LC];

// ---------------- threefry2x32 (20 rounds) ----------------
__device__ __forceinline__ unsigned rotl32(unsigned v, int s) {
    return (v << s) | (v >> (32 - s));
}
__device__ __forceinline__ void threefry2x32(unsigned k0, unsigned k1,
                                             unsigned &x0, unsigned &x1) {
    unsigned ks0 = k0, ks1 = k1, ks2 = k0 ^ k1 ^ 0x1BD11BDAu;
    x0 += ks0; x1 += ks1;
#define TF_R(r) { x0 += x1; x1 = rotl32(x1, (r)); x1 ^= x0; }
    TF_R(13) TF_R(15) TF_R(26) TF_R(6)   x0 += ks1; x1 += ks2 + 1u;
    TF_R(17) TF_R(29) TF_R(16) TF_R(24)  x0 += ks2; x1 += ks0 + 2u;
    TF_R(13) TF_R(15) TF_R(26) TF_R(6)   x0 += ks0; x1 += ks1 + 3u;
    TF_R(17) TF_R(29) TF_R(16) TF_R(24)  x0 += ks1; x1 += ks2 + 4u;
    TF_R(13) TF_R(15) TF_R(26) TF_R(6)   x0 += ks2; x1 += ks0 + 5u;
#undef TF_R
}

__device__ void bitonic4096(unsigned long long *kc, int tid) {
    for (int k = 2; k <= 4096; k <<= 1) {
        for (int j = k >> 1; j > 0; j >>= 1) {
            for (int t = tid; t < 4096; t += 1024) {
                int ixj = t ^ j;
                if (ixj > t) {
                    unsigned long long a = kc[t], b = kc[ixj];
                    bool up = ((t & k) == 0);
                    if ((a > b) == up) { kc[t] = b; kc[ixj] = a; }
                }
            }
            __syncthreads();
        }
    }
}

// reproduce jax.random.permutation(split(key(42),8)[r], 4096)[:64]
__global__ __launch_bounds__(1024) void init_kernel() {
    __shared__ unsigned long long kc[4096];
    __shared__ unsigned perm1[4096];
    int r = blockIdx.x, tid = threadIdx.x;

    unsigned K0 = 0u, K1 = (unsigned)r;
    threefry2x32(0u, 42u, K0, K1);
    unsigned n0 = 0u, n1 = 0u;   threefry2x32(K0, K1, n0, n1);
    unsigned s1a = 0u, s1b = 1u; threefry2x32(K0, K1, s1a, s1b);
    unsigned s2a = 0u, s2b = 1u; threefry2x32(n0, n1, s2a, s2b);

    for (int i = tid; i < 4096; i += 1024) {
        unsigned a = 0u, b = (unsigned)i;
        threefry2x32(s1a, s1b, a, b);
        kc[i] = ((unsigned long long)(a ^ b) << 32) | (unsigned)i;
    }
    __syncthreads();
    bitonic4096(kc, tid);
    for (int i = tid; i < 4096; i += 1024)
        perm1[i] = (unsigned)(kc[i] & 0xffffffffu);
    __syncthreads();

    for (int i = tid; i < 4096; i += 1024) {
        unsigned a = 0u, b = (unsigned)i;
        threefry2x32(s2a, s2b, a, b);
        kc[i] = ((unsigned long long)(a ^ b) << 32) | (unsigned)i;
    }
    __syncthreads();
    bitonic4096(kc, tid);
    if (tid < 64)
        g_init_idx[r * 64 + tid] = (int)perm1[(unsigned)(kc[tid] & 0xffffffffu)];
}

// ---------------- x2: flat sequential sum of squares per point ----------------
__global__ __launch_bounds__(128) void x2_kernel(const float *__restrict__ x) {
    __shared__ float s[SD];
    int p = blockIdx.x;
    const float *row = x + (size_t)p * SD;
    for (int d = threadIdx.x; d < SD; d += 128) s[d] = row[d];
    __syncthreads();
    if (threadIdx.x == 0) {
        float ss = 0.f;
        for (int d = 0; d < SD; ++d) ss = __fadd_rn(ss, __fmul_rn(s[d], s[d]));
        g_x2[p] = ss;
    }
}

// centers[r][l] = pts[r][init_idx]; fused flat-sequential c2
__global__ __launch_bounds__(128) void gather_init_kernel(const float *__restrict__ x) {
    __shared__ float s[SD];
    int b = blockIdx.x, r = b >> 6, tid = threadIdx.x;
    int idx = g_init_idx[b];
    const float *src = x + ((size_t)(r * NP + idx)) * SD;
    size_t base = ((size_t)b) << 10;
    for (int d = tid; d < SD; d += 128) {
        float v = src[d];
        g_centers[base + d] = v;
        s[d] = v;
    }
    __syncthreads();
    if (tid == 0) {
        float ss = 0.f;
        for (int d = 0; d < SD; ++d) ss = __fadd_rn(ss, __fmul_rn(s[d], s[d]));
        g_c2[b] = ss;
    }
}

__global__ void zero_counts_kernel() {
    int i = blockIdx.x * blockDim.x + threadIdx.x;
    if (i < RG * LC) g_counts[i] = 0;
}

// ---------------- assign: argmin_l fl(fl(x2+c2[l]) - 2*dot) ----------------
// block = 128 points x 64 centers; 256 threads; thread tile 4x8; K-chunks of 32
// dot accumulation: single fma chain, strictly ascending k (matches sgemm)
__global__ __launch_bounds__(256) void assign_kernel(const float *__restrict__ x) {
    __shared__ float pT[32][132];
    __shared__ float cT[32][64];
    __shared__ float rv[8][128];
    __shared__ int   ri[8][128];

    int bx = blockIdx.x;
    int r = bx >> 5, tile = bx & 31;
    int pbase = tile * 128;
    const float *pts = x + ((size_t)r * NP) * SD;
    const float *ctr = g_centers + ((size_t)r * LC) * SD;
    int tid = threadIdx.x;
    int pc = tid & 31, cc = tid >> 5;

    float acc[4][8];
#pragma unroll
    for (int i = 0; i < 4; i++)
#pragma unroll
        for (int j = 0; j < 8; j++) acc[i][j] = 0.f;

    for (int k0 = 0; k0 < SD; k0 += 32) {
#pragma unroll
        for (int pass = 0; pass < 4; ++pass) {
            int n  = (tid >> 3) + pass * 32;
            int kq = (tid & 7) * 4;
            float4 v = *(const float4 *)&pts[(size_t)(pbase + n) * SD + k0 + kq];
            pT[kq + 0][n] = v.x; pT[kq + 1][n] = v.y;
            pT[kq + 2][n] = v.z; pT[kq + 3][n] = v.w;
        }
#pragma unroll
        for (int pass = 0; pass < 2; ++pass) {
            int c  = (tid >> 3) + pass * 32;
            int kq = (tid & 7) * 4;
            float4 v = *(const float4 *)&ctr[(size_t)c * SD + k0 + kq];
            cT[kq + 0][c] = v.x; cT[kq + 1][c] = v.y;
            cT[kq + 2][c] = v.z; cT[kq + 3][c] = v.w;
        }
        __syncthreads();
#pragma unroll 8
        for (int kk = 0; kk < 32; ++kk) {
            float4 p  = *(const float4 *)&pT[kk][pc * 4];
            float4 c0 = *(const float4 *)&cT[kk][cc * 8];
            float4 c1 = *(const float4 *)&cT[kk][cc * 8 + 4];
            float pv[4] = {p.x, p.y, p.z, p.w};
            float cv[8] = {c0.x, c0.y, c0.z, c0.w, c1.x, c1.y, c1.z, c1.w};
#pragma unroll
            for (int i = 0; i < 4; i++)
#pragma unroll
                for (int j = 0; j < 8; j++)
                    acc[i][j] = fmaf(pv[i], cv[j], acc[i][j]);
        }
        __syncthreads();
    }

    float c2s[8];
#pragma unroll
    for (int j = 0; j < 8; j++) c2s[j] = g_c2[r * 64 + cc * 8 + j];
#pragma unroll
    for (int i = 0; i < 4; i++) {
        float x2v = g_x2[r * NP + pbase + pc * 4 + i];
        float bv;
        int bj = 0;
        {
            float s = __fadd_rn(x2v, c2s[0]);
            bv = __fadd_rn(s, __fmul_rn(-2.f, acc[i][0]));
        }
#pragma unroll
        for (int j = 1; j < 8; j++) {
            float s = __fadd_rn(x2v, c2s[j]);
            float v = __fadd_rn(s, __fmul_rn(-2.f, acc[i][j]));
            if (v < bv) { bv = v; bj = j; }
        }
        rv[cc][pc * 4 + i] = bv;
        ri[cc][pc * 4 + i] = cc * 8 + bj;
    }
    __syncthreads();
    if (tid < 128) {   // ascending cc keeps first-occurrence on ties (argmin rule)
        float bv = rv[0][tid];
        int bi = ri[0][tid];
#pragma unroll
        for (int g = 1; g < 8; ++g) {
            float v = rv[g][tid];
            if (v < bv) { bv = v; bi = ri[g][tid]; }
        }
        g_labels[r * NP + pbase + tid] = bi;
        atomicAdd(&g_counts[r * 64 + bi], 1);
    }
}

// ---------------- centroid sums: flat sequential over n (one add chain per (l,d)) ---
// fl(acc + 0.0) == acc exactly, so skipping non-members == one-hot GEMM chain.
__global__ __launch_bounds__(128) void accum_kernel(const float *__restrict__ x) {
    __shared__ float acc[64][128];
    __shared__ int lab[128];
    int b = blockIdx.x;          // r*8 + dchunk
    int r = b >> 3, dc = b & 7;
    int tid = threadIdx.x;
#pragma unroll
    for (int c = 0; c < 64; c++) acc[c][tid] = 0.f;
    int d = dc * 128 + tid;
    for (int j0 = 0; j0 < NP; j0 += 128) {
        __syncthreads();
        lab[tid] = g_labels[r * NP + j0 + tid];
        __syncthreads();
#pragma unroll 4
        for (int j = 0; j < 128; ++j)
            acc[lab[j]][tid] = __fadd_rn(acc[lab[j]][tid],
                                         x[(size_t)(r * NP + j0 + j) * SD + d]);
    }
    __syncthreads();
#pragma unroll
    for (int c = 0; c < 64; c++)
        g_sums[(((size_t)(r * 64 + c)) << 10) + d] = acc[c][tid];
}

// centers = sums / count (IEEE div) or keep old; fused flat-sequential c2
__global__ __launch_bounds__(128) void finalize_kernel() {
    __shared__ float s[SD];
    int b = blockIdx.x;          // r*64 + l
    int tid = threadIdx.x;
    int cnt = g_counts[b];
    size_t base = ((size_t)b) << 10;
    float fcnt = (float)cnt;
#pragma unroll
    for (int k = 0; k < 8; k++) {
        int d = k * 128 + tid;
        float v;
        if (cnt > 0) v = __fdiv_rn(g_sums[base + d], fcnt);
        else         v = g_centers[base + d];
        g_centers[base + d] = v;
        s[d] = v;
    }
    __syncthreads();
    if (tid == 0) {
        float ss = 0.f;
        for (int d = 0; d < SD; ++d) ss = __fadd_rn(ss, __fmul_rn(s[d], s[d]));
        g_c2[b] = ss;
    }
}

// out[r,n,:] = centers[r, labels[r,n], :]
__global__ __launch_bounds__(256) void output_kernel(float *__restrict__ out) {
    int b = blockIdx.x;          // r*NP + n
    int lab = g_labels[b];
    int r = b >> 12;
    const float4 *src = (const float4 *)(g_centers + (((size_t)(r * 64 + lab)) << 10));
    float4 *dst = (float4 *)(out + ((size_t)b << 10));
    dst[threadIdx.x] = src[threadIdx.x];
}

extern "C" void kernel_launch(void* const* d_in, const int* in_sizes, int n_in,
                              void* d_out, int out_size) {
    const float *x = (const float *)d_in[0];
    float *out = (float *)d_out;
    (void)in_sizes; (void)n_in; (void)out_size;

    init_kernel<<<RG, 1024>>>();
    x2_kernel<<<RG * NP, 128>>>(x);
    gather_init_kernel<<<RG * LC, 128>>>(x);
    for (int it = 0; it < 10; ++it) {
        zero_counts_kernel<<<1, 512>>>();
        assign_kernel<<<RG * 32, 256>>>(x);
        accum_kernel<<<RG * 8, 128>>>(x);
        finalize_kernel<<<RG * LC, 128>>>();
    }
    zero_counts_kernel<<<1, 512>>>();
    assign_kernel<<<RG * 32, 256>>>(x);
    output_kernel<<<RG * NP, 256>>>(out);
}

// round 5
// speedup vs baseline: 1.4578x; 1.4578x over previous
#include <cuda_runtime.h>

#define RG 8
#define LC 64
#define NP 4096
#define SD 1024

// ---------------- device scratch ----------------
__device__ float g_centers[RG * LC * SD];
__device__ float g_c2[RG * LC];
__device__ float g_x2[RG * NP];
__device__ int   g_counts[RG * LC];
__device__ int   g_offsets[RG * LC];          // CSR start per cluster
__device__ int   g_labels[RG * NP];
__device__ int   g_init_idx[RG * LC];
__device__ int   g_members[RG * NP];          // CSR member lists (128 KB)

// ---------------- f32x2 helpers (each lane = independent IEEE rn fp32) ------
__device__ __forceinline__ unsigned long long fma2(unsigned long long a,
                                                   unsigned long long b,
                                                   unsigned long long c) {
    unsigned long long d;
    asm("fma.rn.f32x2 %0, %1, %2, %3;" : "=l"(d) : "l"(a), "l"(b), "l"(c));
    return d;
}
__device__ __forceinline__ unsigned long long pack2(float lo, float hi) {
    unsigned long long d;
    asm("mov.b64 %0, {%1, %2};" : "=l"(d) : "f"(lo), "f"(hi));
    return d;
}
__device__ __forceinline__ void unpack2(unsigned long long v, float &lo, float &hi) {
    asm("mov.b64 {%0, %1}, %2;" : "=f"(lo), "=f"(hi) : "l"(v));
}

// ---------------- threefry2x32 (20 rounds) ----------------
__device__ __forceinline__ unsigned rotl32(unsigned v, int s) {
    return (v << s) | (v >> (32 - s));
}
__device__ __forceinline__ void threefry2x32(unsigned k0, unsigned k1,
                                             unsigned &x0, unsigned &x1) {
    unsigned ks0 = k0, ks1 = k1, ks2 = k0 ^ k1 ^ 0x1BD11BDAu;
    x0 += ks0; x1 += ks1;
#define TF_R(r) { x0 += x1; x1 = rotl32(x1, (r)); x1 ^= x0; }
    TF_R(13) TF_R(15) TF_R(26) TF_R(6)   x0 += ks1; x1 += ks2 + 1u;
    TF_R(17) TF_R(29) TF_R(16) TF_R(24)  x0 += ks2; x1 += ks0 + 2u;
    TF_R(13) TF_R(15) TF_R(26) TF_R(6)   x0 += ks0; x1 += ks1 + 3u;
    TF_R(17) TF_R(29) TF_R(16) TF_R(24)  x0 += ks1; x1 += ks2 + 4u;
    TF_R(13) TF_R(15) TF_R(26) TF_R(6)   x0 += ks2; x1 += ks0 + 5u;
#undef TF_R
}

__device__ void bitonic4096(unsigned long long *kc, int tid) {
    for (int k = 2; k <= 4096; k <<= 1) {
        for (int j = k >> 1; j > 0; j >>= 1) {
            for (int t = tid; t < 4096; t += 1024) {
                int ixj = t ^ j;
                if (ixj > t) {
                    unsigned long long a = kc[t], b = kc[ixj];
                    bool up = ((t & k) == 0);
                    if ((a > b) == up) { kc[t] = b; kc[ixj] = a; }
                }
            }
            __syncthreads();
        }
    }
}

// reproduce jax.random.permutation(split(key(42),8)[r], 4096)[:64]
__global__ __launch_bounds__(1024) void init_kernel() {
    __shared__ unsigned long long kc[4096];
    __shared__ unsigned perm1[4096];
    int r = blockIdx.x, tid = threadIdx.x;

    unsigned K0 = 0u, K1 = (unsigned)r;
    threefry2x32(0u, 42u, K0, K1);
    unsigned n0 = 0u, n1 = 0u;   threefry2x32(K0, K1, n0, n1);
    unsigned s1a = 0u, s1b = 1u; threefry2x32(K0, K1, s1a, s1b);
    unsigned s2a = 0u, s2b = 1u; threefry2x32(n0, n1, s2a, s2b);

    for (int i = tid; i < 4096; i += 1024) {
        unsigned a = 0u, b = (unsigned)i;
        threefry2x32(s1a, s1b, a, b);
        kc[i] = ((unsigned long long)(a ^ b) << 32) | (unsigned)i;
    }
    __syncthreads();
    bitonic4096(kc, tid);
    for (int i = tid; i < 4096; i += 1024)
        perm1[i] = (unsigned)(kc[i] & 0xffffffffu);
    __syncthreads();

    for (int i = tid; i < 4096; i += 1024) {
        unsigned a = 0u, b = (unsigned)i;
        threefry2x32(s2a, s2b, a, b);
        kc[i] = ((unsigned long long)(a ^ b) << 32) | (unsigned)i;
    }
    __syncthreads();
    bitonic4096(kc, tid);
    if (tid < 64)
        g_init_idx[r * 64 + tid] = (int)perm1[(unsigned)(kc[tid] & 0xffffffffu)];
}

// ---------------- x2: flat sequential sum of squares per point ----------------
__global__ __launch_bounds__(128) void x2_kernel(const float *__restrict__ x) {
    __shared__ float s[SD];
    int p = blockIdx.x;
    const float *row = x + (size_t)p * SD;
    for (int d = threadIdx.x; d < SD; d += 128) s[d] = row[d];
    __syncthreads();
    if (threadIdx.x == 0) {
        float ss = 0.f;
        for (int d = 0; d < SD; ++d) ss = __fadd_rn(ss, __fmul_rn(s[d], s[d]));
        g_x2[p] = ss;
    }
}

// centers[r][l] = pts[r][init_idx]; fused flat-sequential c2
__global__ __launch_bounds__(128) void gather_init_kernel(const float *__restrict__ x) {
    __shared__ float s[SD];
    int b = blockIdx.x, r = b >> 6, tid = threadIdx.x;
    int idx = g_init_idx[b];
    const float *src = x + ((size_t)(r * NP + idx)) * SD;
    size_t base = ((size_t)b) << 10;
    for (int d = tid; d < SD; d += 128) {
        float v = src[d];
        g_centers[base + d] = v;
        s[d] = v;
    }
    __syncthreads();
    if (tid == 0) {
        float ss = 0.f;
        for (int d = 0; d < SD; ++d) ss = __fadd_rn(ss, __fmul_rn(s[d], s[d]));
        g_c2[b] = ss;
    }
}

// ---------------- assign: argmin_l fl(fl(x2+c2[l]) - 2*dot) ----------------
// block = 128 points x 64 centers; 256 threads; thread tile 8pt x 4ctr (f32x2).
// dot: single fma chain, strictly ascending k (identical values to scalar FFMA).
__global__ __launch_bounds__(256) void assign_kernel(const float *__restrict__ x) {
    __shared__ float pT[32][132];
    __shared__ float cT[32][64];
    __shared__ float rv[16][128];
    __shared__ int   ri[16][128];

    int bx = blockIdx.x;
    int r = bx >> 5, tile = bx & 31;
    int pbase = tile * 128;
    const float *pts = x + ((size_t)r * NP) * SD;
    const float *ctr = g_centers + ((size_t)r * LC) * SD;
    int tid = threadIdx.x;
    int pc = tid & 15;          // 16 point groups of 8
    int cc = tid >> 4;          // 16 center groups of 4

    unsigned long long acc[8][2];
#pragma unroll
    for (int i = 0; i < 8; i++) { acc[i][0] = 0ull; acc[i][1] = 0ull; }

    for (int k0 = 0; k0 < SD; k0 += 32) {
#pragma unroll
        for (int pass = 0; pass < 4; ++pass) {
            int n  = (tid >> 3) + pass * 32;
            int kq = (tid & 7) * 4;
            float4 v = *(const float4 *)&pts[(size_t)(pbase + n) * SD + k0 + kq];
            pT[kq + 0][n] = v.x; pT[kq + 1][n] = v.y;
            pT[kq + 2][n] = v.z; pT[kq + 3][n] = v.w;
        }
#pragma unroll
        for (int pass = 0; pass < 2; ++pass) {
            int c  = (tid >> 3) + pass * 32;
            int kq = (tid & 7) * 4;
            float4 v = *(const float4 *)&ctr[(size_t)c * SD + k0 + kq];
            cT[kq + 0][c] = v.x; cT[kq + 1][c] = v.y;
            cT[kq + 2][c] = v.z; cT[kq + 3][c] = v.w;
        }
        __syncthreads();
#pragma unroll 8
        for (int kk = 0; kk < 32; ++kk) {
            const float *pp = &pT[kk][pc * 8];
            float4 pa = *(const float4 *)pp;
            float4 pb = *(const float4 *)(pp + 4);
            float4 cv = *(const float4 *)&cT[kk][cc * 4];
            unsigned long long b01 = pack2(cv.x, cv.y);
            unsigned long long b23 = pack2(cv.z, cv.w);
            float pvs[8] = {pa.x, pa.y, pa.z, pa.w, pb.x, pb.y, pb.z, pb.w};
#pragma unroll
            for (int i = 0; i < 8; i++) {
                unsigned long long a = pack2(pvs[i], pvs[i]);
                acc[i][0] = fma2(a, b01, acc[i][0]);
                acc[i][1] = fma2(a, b23, acc[i][1]);
            }
        }
        __syncthreads();
    }

    float c2s[4];
#pragma unroll
    for (int j = 0; j < 4; j++) c2s[j] = g_c2[r * 64 + cc * 4 + j];
#pragma unroll
    for (int i = 0; i < 8; i++) {
        int p = pc * 8 + i;
        float x2v = g_x2[r * NP + pbase + p];
        float dots[4];
        unpack2(acc[i][0], dots[0], dots[1]);
        unpack2(acc[i][1], dots[2], dots[3]);
        float bv;
        int bj = 0;
        {
            float s = __fadd_rn(x2v, c2s[0]);
            bv = __fadd_rn(s, __fmul_rn(-2.f, dots[0]));
        }
#pragma unroll
        for (int j = 1; j < 4; j++) {
            float s = __fadd_rn(x2v, c2s[j]);
            float v = __fadd_rn(s, __fmul_rn(-2.f, dots[j]));
            if (v < bv) { bv = v; bj = j; }   // strict < keeps first-min
        }
        rv[cc][p] = bv;
        ri[cc][p] = cc * 4 + bj;
    }
    __syncthreads();
    if (tid < 128) {   // ascending cc keeps lowest center index on ties
        float bv = rv[0][tid];
        int bi = ri[0][tid];
#pragma unroll
        for (int g = 1; g < 16; ++g) {
            float v = rv[g][tid];
            if (v < bv) { bv = v; bi = ri[g][tid]; }
        }
        g_labels[r * NP + pbase + tid] = bi;
    }
}

// ------------- deterministic counting sort: CSR member lists ---------
// 512 threads = 64 clusters x 8 n-chunks of 512; chunk order fixed -> ascending n.
__global__ __launch_bounds__(512) void build_lists_kernel() {
    __shared__ int lab[NP];          // 16 KB
    __shared__ int cnt[64][8];
    __shared__ int ctot[64];
    int r = blockIdx.x, tid = threadIdx.x;
    for (int i = tid; i < NP; i += 512) lab[i] = g_labels[r * NP + i];
    __syncthreads();
    int c = tid & 63, ch = tid >> 6;     // warp lanes share ch -> broadcast LDS
    int base = ch * 512;
    int n0 = 0;
    for (int i = 0; i < 512; ++i) n0 += (lab[base + i] == c);
    cnt[c][ch] = n0;
    __syncthreads();
    if (ch == 0) {
        int t = 0;
#pragma unroll
        for (int k = 0; k < 8; k++) t += cnt[c][k];
        g_counts[r * 64 + c] = t;
        ctot[c] = t;
    }
    __syncthreads();
    // exclusive prefix over clusters (redundant per thread; 64 adds)
    int coff = 0;
    for (int k = 0; k < c; ++k) coff += ctot[k];
    if (ch == 0) g_offsets[r * 64 + c] = coff;
    int pos = coff;
    for (int k = 0; k < ch; k++) pos += cnt[c][k];
    int *dst = &g_members[r * NP];
    for (int i = 0; i < 512; ++i) {
        int n = base + i;
        if (lab[n] == c) dst[pos++] = n;
    }
}

// ------- sums over members (ascending n, identical chain to R3) + finalize ----
__global__ __launch_bounds__(128) void sum_finalize_kernel(const float *__restrict__ x) {
    __shared__ int mem[NP];          // 16 KB
    __shared__ float s[SD];
    int b = blockIdx.x;              // r*64 + l
    int r = b >> 6, tid = threadIdx.x;
    int cnt = g_counts[b];
    int off = g_offsets[b];
    size_t cbase = ((size_t)b) << 10;
    for (int i = tid; i < cnt; i += 128) mem[i] = g_members[r * NP + off + i];
    __syncthreads();

    float acc[8];
#pragma unroll
    for (int k = 0; k < 8; k++) acc[k] = 0.f;
    const float *xr = x + ((size_t)r * NP) * SD;
#pragma unroll 2
    for (int m = 0; m < cnt; ++m) {
        const float *row = xr + ((size_t)mem[m]) * SD;
#pragma unroll
        for (int k = 0; k < 8; k++)
            acc[k] = __fadd_rn(acc[k], row[tid + k * 128]);
    }
    float fcnt = (float)cnt;
#pragma unroll
    for (int k = 0; k < 8; k++) {
        int d = tid + k * 128;
        float v = (cnt > 0) ? __fdiv_rn(acc[k], fcnt) : g_centers[cbase + d];
        g_centers[cbase + d] = v;
        s[d] = v;
    }
    __syncthreads();
    if (tid == 0) {
        float ss = 0.f;
        for (int d = 0; d < SD; ++d) ss = __fadd_rn(ss, __fmul_rn(s[d], s[d]));
        g_c2[b] = ss;
    }
}

// out[r,n,:] = centers[r, labels[r,n], :]
__global__ __launch_bounds__(256) void output_kernel(float *__restrict__ out) {
    int b = blockIdx.x;              // r*NP + n
    int lab = g_labels[b];
    int r = b >> 12;
    const float4 *src = (const float4 *)(g_centers + (((size_t)(r * 64 + lab)) << 10));
    float4 *dst = (float4 *)(out + ((size_t)b << 10));
    dst[threadIdx.x] = src[threadIdx.x];
}

extern "C" void kernel_launch(void* const* d_in, const int* in_sizes, int n_in,
                              void* d_out, int out_size) {
    const float *x = (const float *)d_in[0];
    float *out = (float *)d_out;
    (void)in_sizes; (void)n_in; (void)out_size;

    init_kernel<<<RG, 1024>>>();
    x2_kernel<<<RG * NP, 128>>>(x);
    gather_init_kernel<<<RG * LC, 128>>>(x);
    for (int it = 0; it < 10; ++it) {
        assign_kernel<<<RG * 32, 256>>>(x);
        build_lists_kernel<<<RG, 512>>>();
        sum_finalize_kernel<<<RG * LC, 128>>>(x);
    }
    assign_kernel<<<RG * 32, 256>>>(x);
    output_kernel<<<RG * NP, 256>>>(out);
}

// round 6
// speedup vs baseline: 1.6381x; 1.1237x over previous
#include <cuda_runtime.h>

#define RG 8
#define LC 64
#define NP 4096
#define SD 1024

// ---------------- device scratch ----------------
__device__ float g_centers[RG * LC * SD];
__device__ float g_c2[RG * LC];
__device__ float g_x2[RG * NP];
__device__ int   g_counts[RG * LC];
__device__ int   g_offsets[RG * LC];
__device__ int   g_labels[RG * NP];
__device__ int   g_init_idx[RG * LC];
__device__ int   g_members[RG * NP];

// ---------------- f32x2 helpers (each lane = independent IEEE rn fp32) ------
__device__ __forceinline__ unsigned long long fma2(unsigned long long a,
                                                   unsigned long long b,
                                                   unsigned long long c) {
    unsigned long long d;
    asm("fma.rn.f32x2 %0, %1, %2, %3;" : "=l"(d) : "l"(a), "l"(b), "l"(c));
    return d;
}
__device__ __forceinline__ unsigned long long pack2(float lo, float hi) {
    unsigned long long d;
    asm("mov.b64 %0, {%1, %2};" : "=l"(d) : "f"(lo), "f"(hi));
    return d;
}
__device__ __forceinline__ void unpack2(unsigned long long v, float &lo, float &hi) {
    asm("mov.b64 {%0, %1}, %2;" : "=f"(lo), "=f"(hi) : "l"(v));
}

// ---------------- threefry2x32 (20 rounds) ----------------
__device__ __forceinline__ unsigned rotl32(unsigned v, int s) {
    return (v << s) | (v >> (32 - s));
}
__device__ __forceinline__ void threefry2x32(unsigned k0, unsigned k1,
                                             unsigned &x0, unsigned &x1) {
    unsigned ks0 = k0, ks1 = k1, ks2 = k0 ^ k1 ^ 0x1BD11BDAu;
    x0 += ks0; x1 += ks1;
#define TF_R(r) { x0 += x1; x1 = rotl32(x1, (r)); x1 ^= x0; }
    TF_R(13) TF_R(15) TF_R(26) TF_R(6)   x0 += ks1; x1 += ks2 + 1u;
    TF_R(17) TF_R(29) TF_R(16) TF_R(24)  x0 += ks2; x1 += ks0 + 2u;
    TF_R(13) TF_R(15) TF_R(26) TF_R(6)   x0 += ks0; x1 += ks1 + 3u;
    TF_R(17) TF_R(29) TF_R(16) TF_R(24)  x0 += ks1; x1 += ks2 + 4u;
    TF_R(13) TF_R(15) TF_R(26) TF_R(6)   x0 += ks2; x1 += ks0 + 5u;
#undef TF_R
}

__device__ void bitonic4096(unsigned long long *kc, int tid) {
    for (int k = 2; k <= 4096; k <<= 1) {
        for (int j = k >> 1; j > 0; j >>= 1) {
            for (int t = tid; t < 4096; t += 1024) {
                int ixj = t ^ j;
                if (ixj > t) {
                    unsigned long long a = kc[t], b = kc[ixj];
                    bool up = ((t & k) == 0);
                    if ((a > b) == up) { kc[t] = b; kc[ixj] = a; }
                }
            }
            __syncthreads();
        }
    }
}

// reproduce jax.random.permutation(split(key(42),8)[r], 4096)[:64]
__global__ __launch_bounds__(1024) void init_kernel() {
    __shared__ unsigned long long kc[4096];
    __shared__ unsigned perm1[4096];
    int r = blockIdx.x, tid = threadIdx.x;

    unsigned K0 = 0u, K1 = (unsigned)r;
    threefry2x32(0u, 42u, K0, K1);
    unsigned n0 = 0u, n1 = 0u;   threefry2x32(K0, K1, n0, n1);
    unsigned s1a = 0u, s1b = 1u; threefry2x32(K0, K1, s1a, s1b);
    unsigned s2a = 0u, s2b = 1u; threefry2x32(n0, n1, s2a, s2b);

    for (int i = tid; i < 4096; i += 1024) {
        unsigned a = 0u, b = (unsigned)i;
        threefry2x32(s1a, s1b, a, b);
        kc[i] = ((unsigned long long)(a ^ b) << 32) | (unsigned)i;
    }
    __syncthreads();
    bitonic4096(kc, tid);
    for (int i = tid; i < 4096; i += 1024)
        perm1[i] = (unsigned)(kc[i] & 0xffffffffu);
    __syncthreads();

    for (int i = tid; i < 4096; i += 1024) {
        unsigned a = 0u, b = (unsigned)i;
        threefry2x32(s2a, s2b, a, b);
        kc[i] = ((unsigned long long)(a ^ b) << 32) | (unsigned)i;
    }
    __syncthreads();
    bitonic4096(kc, tid);
    if (tid < 64)
        g_init_idx[r * 64 + tid] = (int)perm1[(unsigned)(kc[tid] & 0xffffffffu)];
}

// ---------------- x2: 8 parallel flat-sequential chains per block ----------------
#define X2ROW 1036   // pad: 1036 mod 32 = 12 -> 8 chain threads hit distinct banks
__global__ __launch_bounds__(128) void x2_kernel(const float *__restrict__ x) {
    __shared__ float s[8 * X2ROW];
    int pb = blockIdx.x * 8;
    const float4 *src = (const float4 *)(x + (size_t)pb * SD);
    for (int i = threadIdx.x; i < 8 * (SD / 4); i += 128) {
        int p = i >> 8, q = i & 255;
        *(float4 *)&s[p * X2ROW + q * 4] = src[p * 256 + q];
    }
    __syncthreads();
    if (threadIdx.x < 8) {
        const float *row = &s[threadIdx.x * X2ROW];
        float ss = 0.f;
#pragma unroll 8
        for (int d = 0; d < SD; ++d)
            ss = __fadd_rn(ss, __fmul_rn(row[d], row[d]));
        g_x2[pb + threadIdx.x] = ss;
    }
}

// centers[r][l] = pts[r][init_idx]; fused flat-sequential c2 (single lane: no conflicts)
__global__ __launch_bounds__(128) void gather_init_kernel(const float *__restrict__ x) {
    __shared__ float s[SD];
    int b = blockIdx.x, r = b >> 6, tid = threadIdx.x;
    int idx = g_init_idx[b];
    const float *src = x + ((size_t)(r * NP + idx)) * SD;
    size_t base = ((size_t)b) << 10;
    for (int d = tid; d < SD; d += 128) {
        float v = src[d];
        g_centers[base + d] = v;
        s[d] = v;
    }
    __syncthreads();
    if (tid == 0) {
        float ss = 0.f;
#pragma unroll 8
        for (int d = 0; d < SD; ++d) ss = __fadd_rn(ss, __fmul_rn(s[d], s[d]));
        g_c2[b] = ss;
    }
}

// ---------------- assign: argmin_l fl(fl(x2+c2[l]) - 2*dot) ----------------
// block = 128 pts x 64 ctrs; 256 threads; tile 8pt x 4ctr; f32x2 lanes = point pair.
// Double-buffered k-chunks of 16; dot = single fma chain, strictly ascending k.
#define KCH 16
__global__ __launch_bounds__(256) void assign_kernel(const float *__restrict__ x) {
    __shared__ float pT[2][KCH][132];
    __shared__ float cT[2][KCH][68];
    __shared__ float rv[16][128];
    __shared__ int   ri[16][128];

    int bx = blockIdx.x;
    int r = bx >> 5, tile = bx & 31;
    int pbase = tile * 128;
    const float *pts = x + ((size_t)r * NP) * SD;
    const float *ctr = g_centers + ((size_t)r * LC) * SD;
    int tid = threadIdx.x;
    int pc = tid & 15;          // 16 point groups of 8
    int cc = tid >> 4;          // 16 center groups of 4

    // staging indices (fixed per thread)
    int sn0 = tid >> 2;         // 0..63  (points pass 0 row, ctr row)
    int skq = (tid & 3) * 4;    // k offset 0,4,8,12

    unsigned long long acc[4][4];
#pragma unroll
    for (int i = 0; i < 4; i++)
#pragma unroll
        for (int j = 0; j < 4; j++) acc[i][j] = 0ull;

    float4 sp0, sp1, sc;
    // stage chunk 0
    sp0 = *(const float4 *)&pts[(size_t)(pbase + sn0) * SD + skq];
    sp1 = *(const float4 *)&pts[(size_t)(pbase + 64 + sn0) * SD + skq];
    sc  = *(const float4 *)&ctr[(size_t)sn0 * SD + skq];
    // store chunk 0 -> buf 0
    pT[0][skq + 0][sn0] = sp0.x; pT[0][skq + 1][sn0] = sp0.y;
    pT[0][skq + 2][sn0] = sp0.z; pT[0][skq + 3][sn0] = sp0.w;
    pT[0][skq + 0][64 + sn0] = sp1.x; pT[0][skq + 1][64 + sn0] = sp1.y;
    pT[0][skq + 2][64 + sn0] = sp1.z; pT[0][skq + 3][64 + sn0] = sp1.w;
    cT[0][skq + 0][sn0] = sc.x; cT[0][skq + 1][sn0] = sc.y;
    cT[0][skq + 2][sn0] = sc.z; cT[0][skq + 3][sn0] = sc.w;
    // stage chunk 1
    sp0 = *(const float4 *)&pts[(size_t)(pbase + sn0) * SD + KCH + skq];
    sp1 = *(const float4 *)&pts[(size_t)(pbase + 64 + sn0) * SD + KCH + skq];
    sc  = *(const float4 *)&ctr[(size_t)sn0 * SD + KCH + skq];
    __syncthreads();

    const int NCHUNK = SD / KCH;   // 64
    for (int c = 0; c < NCHUNK; ++c) {
        int cur = c & 1;
        if (c + 1 < NCHUNK) {
            int nb = 1 - cur;
            pT[nb][skq + 0][sn0] = sp0.x; pT[nb][skq + 1][sn0] = sp0.y;
            pT[nb][skq + 2][sn0] = sp0.z; pT[nb][skq + 3][sn0] = sp0.w;
            pT[nb][skq + 0][64 + sn0] = sp1.x; pT[nb][skq + 1][64 + sn0] = sp1.y;
            pT[nb][skq + 2][64 + sn0] = sp1.z; pT[nb][skq + 3][64 + sn0] = sp1.w;
            cT[nb][skq + 0][sn0] = sc.x; cT[nb][skq + 1][sn0] = sc.y;
            cT[nb][skq + 2][sn0] = sc.z; cT[nb][skq + 3][sn0] = sc.w;
            if (c + 2 < NCHUNK) {
                int k0 = (c + 2) * KCH;
                sp0 = *(const float4 *)&pts[(size_t)(pbase + sn0) * SD + k0 + skq];
                sp1 = *(const float4 *)&pts[(size_t)(pbase + 64 + sn0) * SD + k0 + skq];
                sc  = *(const float4 *)&ctr[(size_t)sn0 * SD + k0 + skq];
            }
        }
#pragma unroll
        for (int kk = 0; kk < KCH; ++kk) {
            ulonglong2 pa = *(const ulonglong2 *)&pT[cur][kk][pc * 8];      // pairs (p0p1,p2p3)
            ulonglong2 pb = *(const ulonglong2 *)&pT[cur][kk][pc * 8 + 4];  // pairs (p4p5,p6p7)
            float4 cv = *(const float4 *)&cT[cur][kk][cc * 4];
            unsigned long long cd[4] = {pack2(cv.x, cv.x), pack2(cv.y, cv.y),
                                        pack2(cv.z, cv.z), pack2(cv.w, cv.w)};
            unsigned long long pp[4] = {pa.x, pa.y, pb.x, pb.y};
#pragma unroll
            for (int i = 0; i < 4; i++)
#pragma unroll
                for (int j = 0; j < 4; j++)
                    acc[i][j] = fma2(pp[i], cd[j], acc[i][j]);
        }
        __syncthreads();
    }

    float c2s[4];
#pragma unroll
    for (int j = 0; j < 4; j++) c2s[j] = g_c2[r * 64 + cc * 4 + j];
#pragma unroll
    for (int i = 0; i < 8; i++) {
        int p = pc * 8 + i;
        float x2v = g_x2[r * NP + pbase + p];
        float dots[4];
#pragma unroll
        for (int j = 0; j < 4; j++) {
            float lo, hi;
            unpack2(acc[i >> 1][j], lo, hi);
            dots[j] = (i & 1) ? hi : lo;
        }
        float bv;
        int bj = 0;
        {
            float s = __fadd_rn(x2v, c2s[0]);
            bv = __fadd_rn(s, __fmul_rn(-2.f, dots[0]));
        }
#pragma unroll
        for (int j = 1; j < 4; j++) {
            float s = __fadd_rn(x2v, c2s[j]);
            float v = __fadd_rn(s, __fmul_rn(-2.f, dots[j]));
            if (v < bv) { bv = v; bj = j; }   // strict < keeps first-min
        }
        rv[cc][p] = bv;
        ri[cc][p] = cc * 4 + bj;
    }
    __syncthreads();
    if (tid < 128) {   // ascending cc keeps lowest center index on ties
        float bv = rv[0][tid];
        int bi = ri[0][tid];
#pragma unroll
        for (int g = 1; g < 16; ++g) {
            float v = rv[g][tid];
            if (v < bv) { bv = v; bi = ri[g][tid]; }
        }
        g_labels[r * NP + pbase + tid] = bi;
    }
}

// ------------- deterministic counting sort: CSR member lists ---------
__global__ __launch_bounds__(512) void build_lists_kernel() {
    __shared__ int lab[NP];
    __shared__ int cnt[64][8];
    __shared__ int ctot[64];
    int r = blockIdx.x, tid = threadIdx.x;
    for (int i = tid; i < NP; i += 512) lab[i] = g_labels[r * NP + i];
    __syncthreads();
    int c = tid & 63, ch = tid >> 6;
    int base = ch * 512;
    int n0 = 0;
#pragma unroll 8
    for (int i = 0; i < 512; ++i) n0 += (lab[base + i] == c);
    cnt[c][ch] = n0;
    __syncthreads();
    if (ch == 0) {
        int t = 0;
#pragma unroll
        for (int k = 0; k < 8; k++) t += cnt[c][k];
        g_counts[r * 64 + c] = t;
        ctot[c] = t;
    }
    __syncthreads();
    int coff = 0;
    for (int k = 0; k < c; ++k) coff += ctot[k];
    if (ch == 0) g_offsets[r * 64 + c] = coff;
    int pos = coff;
    for (int k = 0; k < ch; k++) pos += cnt[c][k];
    int *dst = &g_members[r * NP];
    for (int i = 0; i < 512; ++i) {
        int n = base + i;
        if (lab[n] == c) dst[pos++] = n;
    }
}

// ------- sums over members (ascending n, bit-identical chain) + finalize ----
__global__ __launch_bounds__(128) void sum_finalize_kernel(const float *__restrict__ x) {
    __shared__ int mem[NP];
    __shared__ float s[SD];
    int b = blockIdx.x;              // r*64 + l
    int r = b >> 6, tid = threadIdx.x;
    int cnt = g_counts[b];
    int off = g_offsets[b];
    size_t cbase = ((size_t)b) << 10;
    for (int i = tid; i < cnt; i += 128) mem[i] = g_members[r * NP + off + i];
    __syncthreads();

    float acc[8];
#pragma unroll
    for (int k = 0; k < 8; k++) acc[k] = 0.f;
    const float *xr = x + ((size_t)r * NP) * SD;
#pragma unroll 4
    for (int m = 0; m < cnt; ++m) {
        const float *row = xr + ((size_t)mem[m]) * SD;
#pragma unroll
        for (int k = 0; k < 8; k++)
            acc[k] = __fadd_rn(acc[k], row[tid + k * 128]);
    }
    float fcnt = (float)cnt;
#pragma unroll
    for (int k = 0; k < 8; k++) {
        int d = tid + k * 128;
        float v = (cnt > 0) ? __fdiv_rn(acc[k], fcnt) : g_centers[cbase + d];
        g_centers[cbase + d] = v;
        s[d] = v;
    }
    __syncthreads();
    if (tid == 0) {
        float ss = 0.f;
#pragma unroll 8
        for (int d = 0; d < SD; ++d) ss = __fadd_rn(ss, __fmul_rn(s[d], s[d]));
        g_c2[b] = ss;
    }
}

// out[r,n,:] = centers[r, labels[r,n], :]
__global__ __launch_bounds__(256) void output_kernel(float *__restrict__ out) {
    int b = blockIdx.x;
    int lab = g_labels[b];
    int r = b >> 12;
    const float4 *src = (const float4 *)(g_centers + (((size_t)(r * 64 + lab)) << 10));
    float4 *dst = (float4 *)(out + ((size_t)b << 10));
    dst[threadIdx.x] = src[threadIdx.x];
}

extern "C" void kernel_launch(void* const* d_in, const int* in_sizes, int n_in,
                              void* d_out, int out_size) {
    const float *x = (const float *)d_in[0];
    float *out = (float *)d_out;
    (void)in_sizes; (void)n_in; (void)out_size;

    init_kernel<<<RG, 1024>>>();
    x2_kernel<<<RG * NP / 8, 128>>>(x);
    gather_init_kernel<<<RG * LC, 128>>>(x);
    for (int it = 0; it < 10; ++it) {
        assign_kernel<<<RG * 32, 256>>>(x);
        build_lists_kernel<<<RG, 512>>>();
        sum_finalize_kernel<<<RG * LC, 128>>>(x);
    }
    assign_kernel<<<RG * 32, 256>>>(x);
    output_kernel<<<RG * NP, 256>>>(out);
}

// round 7
// speedup vs baseline: 1.8182x; 1.1099x over previous
#include <cuda_runtime.h>

#define RG 8
#define LC 64
#define NP 4096
#define SD 1024

// ---------------- device scratch ----------------
__device__ float g_centers[RG * LC * SD];
__device__ float g_c2[RG * LC];
__device__ float g_x2[RG * NP];
__device__ int   g_counts[RG * LC];
__device__ int   g_offsets[RG * LC];
__device__ int   g_labels[RG * NP];
__device__ int   g_init_idx[RG * LC];
__device__ int   g_members[RG * NP];

// ---------------- f32x2 helpers (each lane = independent IEEE rn fp32) ------
__device__ __forceinline__ unsigned long long fma2(unsigned long long a,
                                                   unsigned long long b,
                                                   unsigned long long c) {
    unsigned long long d;
    asm("fma.rn.f32x2 %0, %1, %2, %3;" : "=l"(d) : "l"(a), "l"(b), "l"(c));
    return d;
}
__device__ __forceinline__ void unpack2(unsigned long long v, float &lo, float &hi) {
    asm("mov.b64 {%0, %1}, %2;" : "=f"(lo), "=f"(hi) : "l"(v));
}

// ---------------- threefry2x32 (20 rounds) ----------------
__device__ __forceinline__ unsigned rotl32(unsigned v, int s) {
    return (v << s) | (v >> (32 - s));
}
__device__ __forceinline__ void threefry2x32(unsigned k0, unsigned k1,
                                             unsigned &x0, unsigned &x1) {
    unsigned ks0 = k0, ks1 = k1, ks2 = k0 ^ k1 ^ 0x1BD11BDAu;
    x0 += ks0; x1 += ks1;
#define TF_R(r) { x0 += x1; x1 = rotl32(x1, (r)); x1 ^= x0; }
    TF_R(13) TF_R(15) TF_R(26) TF_R(6)   x0 += ks1; x1 += ks2 + 1u;
    TF_R(17) TF_R(29) TF_R(16) TF_R(24)  x0 += ks2; x1 += ks0 + 2u;
    TF_R(13) TF_R(15) TF_R(26) TF_R(6)   x0 += ks0; x1 += ks1 + 3u;
    TF_R(17) TF_R(29) TF_R(16) TF_R(24)  x0 += ks1; x1 += ks2 + 4u;
    TF_R(13) TF_R(15) TF_R(26) TF_R(6)   x0 += ks2; x1 += ks0 + 5u;
#undef TF_R
}

__device__ void bitonic4096(unsigned long long *kc, int tid) {
    for (int k = 2; k <= 4096; k <<= 1) {
        for (int j = k >> 1; j > 0; j >>= 1) {
            for (int t = tid; t < 4096; t += 1024) {
                int ixj = t ^ j;
                if (ixj > t) {
                    unsigned long long a = kc[t], b = kc[ixj];
                    bool up = ((t & k) == 0);
                    if ((a > b) == up) { kc[t] = b; kc[ixj] = a; }
                }
            }
            __syncthreads();
        }
    }
}

// reproduce jax.random.permutation(split(key(42),8)[r], 4096)[:64]
__global__ __launch_bounds__(1024) void init_kernel() {
    __shared__ unsigned long long kc[4096];
    __shared__ unsigned perm1[4096];
    int r = blockIdx.x, tid = threadIdx.x;

    unsigned K0 = 0u, K1 = (unsigned)r;
    threefry2x32(0u, 42u, K0, K1);
    unsigned n0 = 0u, n1 = 0u;   threefry2x32(K0, K1, n0, n1);
    unsigned s1a = 0u, s1b = 1u; threefry2x32(K0, K1, s1a, s1b);
    unsigned s2a = 0u, s2b = 1u; threefry2x32(n0, n1, s2a, s2b);

    for (int i = tid; i < 4096; i += 1024) {
        unsigned a = 0u, b = (unsigned)i;
        threefry2x32(s1a, s1b, a, b);
        kc[i] = ((unsigned long long)(a ^ b) << 32) | (unsigned)i;
    }
    __syncthreads();
    bitonic4096(kc, tid);
    for (int i = tid; i < 4096; i += 1024)
        perm1[i] = (unsigned)(kc[i] & 0xffffffffu);
    __syncthreads();

    for (int i = tid; i < 4096; i += 1024) {
        unsigned a = 0u, b = (unsigned)i;
        threefry2x32(s2a, s2b, a, b);
        kc[i] = ((unsigned long long)(a ^ b) << 32) | (unsigned)i;
    }
    __syncthreads();
    bitonic4096(kc, tid);
    if (tid < 64)
        g_init_idx[r * 64 + tid] = (int)perm1[(unsigned)(kc[tid] & 0xffffffffu)];
}

// ---------------- x2: 8 parallel flat-sequential chains per block ----------------
#define X2ROW 1036
__global__ __launch_bounds__(128) void x2_kernel(const float *__restrict__ x) {
    __shared__ __align__(16) float s[8 * X2ROW];
    int pb = blockIdx.x * 8;
    const float4 *src = (const float4 *)(x + (size_t)pb * SD);
    for (int i = threadIdx.x; i < 8 * (SD / 4); i += 128) {
        int p = i >> 8, q = i & 255;
        *(float4 *)&s[p * X2ROW + q * 4] = src[p * 256 + q];
    }
    __syncthreads();
    if (threadIdx.x < 8) {
        const float *row = &s[threadIdx.x * X2ROW];
        float ss = 0.f;
#pragma unroll 8
        for (int d = 0; d < SD; ++d)
            ss = __fadd_rn(ss, __fmul_rn(row[d], row[d]));
        g_x2[pb + threadIdx.x] = ss;
    }
}

// centers[r][l] = pts[r][init_idx]; fused flat-sequential c2
__global__ __launch_bounds__(128) void gather_init_kernel(const float *__restrict__ x) {
    __shared__ float s[SD];
    int b = blockIdx.x, r = b >> 6, tid = threadIdx.x;
    int idx = g_init_idx[b];
    const float *src = x + ((size_t)(r * NP + idx)) * SD;
    size_t base = ((size_t)b) << 10;
    for (int d = tid; d < SD; d += 128) {
        float v = src[d];
        g_centers[base + d] = v;
        s[d] = v;
    }
    __syncthreads();
    if (tid == 0) {
        float ss = 0.f;
#pragma unroll 8
        for (int d = 0; d < SD; ++d) ss = __fadd_rn(ss, __fmul_rn(s[d], s[d]));
        g_c2[b] = ss;
    }
}

// ---------------- assign: argmin_l fl(fl(x2+c2[l]) - 2*dot) ----------------
// block = 256 pts x 64 ctrs; 256 threads; thread tile 8pt x 8ctr.
// f32x2 lanes = adjacent point pair; centers pre-duplicated (c,c) in smem.
// Dot = single fma chain, strictly ascending k. Grid = 128 (one wave).
#define KCH 8
#define BPT 256
__global__ __launch_bounds__(256) void assign_kernel(const float *__restrict__ x) {
    __shared__ __align__(16) float pT[2][KCH][BPT];    // 16 KB
    __shared__ __align__(16) float cTd[2][KCH][128];   // 8 KB (dup centers)
    __shared__ float rv[8][BPT];                       // 8 KB
    __shared__ int   ri[8][BPT];                       // 8 KB

    int bx = blockIdx.x;
    int r = bx >> 4, tile = bx & 15;
    int pbase = tile * BPT;
    const float *pts = x + ((size_t)r * NP) * SD;
    const float *ctr = g_centers + ((size_t)r * LC) * SD;
    int tid = threadIdx.x;
    int pc = tid & 31;          // 32 point groups of 8 (split 4+4)
    int cc = tid >> 5;          // 8 warps = 8 center groups of 8

    const float *prow = pts + (size_t)(pbase + tid) * SD;
    bool cload = tid < 128;
    int sc_c = tid & 63, sc_h = (tid >> 6) & 1;
    const float *crow = ctr + (size_t)sc_c * SD + sc_h * 4;

    unsigned long long acc[4][8];
#pragma unroll
    for (int i = 0; i < 4; i++)
#pragma unroll
        for (int j = 0; j < 8; j++) acc[i][j] = 0ull;

    float4 sp0, sp1, sc;
    // load + store chunk 0 into buf 0
    sp0 = *(const float4 *)(prow + 0);
    sp1 = *(const float4 *)(prow + 4);
    if (cload) sc = *(const float4 *)(crow + 0);
    {
        pT[0][0][tid] = sp0.x; pT[0][1][tid] = sp0.y;
        pT[0][2][tid] = sp0.z; pT[0][3][tid] = sp0.w;
        pT[0][4][tid] = sp1.x; pT[0][5][tid] = sp1.y;
        pT[0][6][tid] = sp1.z; pT[0][7][tid] = sp1.w;
        if (cload) {
            int kb = sc_h * 4, c2i = sc_c * 2;
            cTd[0][kb + 0][c2i] = sc.x; cTd[0][kb + 0][c2i + 1] = sc.x;
            cTd[0][kb + 1][c2i] = sc.y; cTd[0][kb + 1][c2i + 1] = sc.y;
            cTd[0][kb + 2][c2i] = sc.z; cTd[0][kb + 2][c2i + 1] = sc.z;
            cTd[0][kb + 3][c2i] = sc.w; cTd[0][kb + 3][c2i + 1] = sc.w;
        }
    }
    // preload chunk 1
    sp0 = *(const float4 *)(prow + KCH + 0);
    sp1 = *(const float4 *)(prow + KCH + 4);
    if (cload) sc = *(const float4 *)(crow + KCH);
    __syncthreads();

    const int NCHUNK = SD / KCH;   // 128
    for (int c = 0; c < NCHUNK; ++c) {
        int cur = c & 1;
        if (c + 1 < NCHUNK) {
            int nb = cur ^ 1;
            pT[nb][0][tid] = sp0.x; pT[nb][1][tid] = sp0.y;
            pT[nb][2][tid] = sp0.z; pT[nb][3][tid] = sp0.w;
            pT[nb][4][tid] = sp1.x; pT[nb][5][tid] = sp1.y;
            pT[nb][6][tid] = sp1.z; pT[nb][7][tid] = sp1.w;
            if (cload) {
                int kb = sc_h * 4, c2i = sc_c * 2;
                cTd[nb][kb + 0][c2i] = sc.x; cTd[nb][kb + 0][c2i + 1] = sc.x;
                cTd[nb][kb + 1][c2i] = sc.y; cTd[nb][kb + 1][c2i + 1] = sc.y;
                cTd[nb][kb + 2][c2i] = sc.z; cTd[nb][kb + 2][c2i + 1] = sc.z;
                cTd[nb][kb + 3][c2i] = sc.w; cTd[nb][kb + 3][c2i + 1] = sc.w;
            }
            if (c + 2 < NCHUNK) {
                int k0 = (c + 2) * KCH;
                sp0 = *(const float4 *)(prow + k0 + 0);
                sp1 = *(const float4 *)(prow + k0 + 4);
                if (cload) sc = *(const float4 *)(crow + k0);
            }
        }
#pragma unroll
        for (int kk = 0; kk < KCH; ++kk) {
            ulonglong2 pa = *(const ulonglong2 *)&pT[cur][kk][pc * 4];
            ulonglong2 pb = *(const ulonglong2 *)&pT[cur][kk][128 + pc * 4];
            ulonglong2 c01 = *(const ulonglong2 *)&cTd[cur][kk][cc * 16 + 0];
            ulonglong2 c23 = *(const ulonglong2 *)&cTd[cur][kk][cc * 16 + 4];
            ulonglong2 c45 = *(const ulonglong2 *)&cTd[cur][kk][cc * 16 + 8];
            ulonglong2 c67 = *(const ulonglong2 *)&cTd[cur][kk][cc * 16 + 12];
            unsigned long long pp[4] = {pa.x, pa.y, pb.x, pb.y};
            unsigned long long cd[8] = {c01.x, c01.y, c23.x, c23.y,
                                        c45.x, c45.y, c67.x, c67.y};
#pragma unroll
            for (int i = 0; i < 4; i++)
#pragma unroll
                for (int j = 0; j < 8; j++)
                    acc[i][j] = fma2(pp[i], cd[j], acc[i][j]);
        }
        __syncthreads();
    }

    float c2s[8];
#pragma unroll
    for (int j = 0; j < 8; j++) c2s[j] = g_c2[r * 64 + cc * 8 + j];
#pragma unroll
    for (int e = 0; e < 8; ++e) {
        int pair = e >> 1, lane = e & 1;
        int p = (e < 4) ? (pc * 4 + e) : (128 + pc * 4 + (e - 4));
        float x2v = g_x2[r * NP + pbase + p];
        float dots[8];
#pragma unroll
        for (int j = 0; j < 8; j++) {
            float lo, hi;
            unpack2(acc[pair][j], lo, hi);
            dots[j] = lane ? hi : lo;
        }
        float bv;
        int bj = 0;
        {
            float sSum = __fadd_rn(x2v, c2s[0]);
            bv = __fadd_rn(sSum, __fmul_rn(-2.f, dots[0]));
        }
#pragma unroll
        for (int j = 1; j < 8; j++) {
            float sSum = __fadd_rn(x2v, c2s[j]);
            float v = __fadd_rn(sSum, __fmul_rn(-2.f, dots[j]));
            if (v < bv) { bv = v; bj = j; }   // strict < keeps first-min
        }
        rv[cc][p] = bv;
        ri[cc][p] = cc * 8 + bj;
    }
    __syncthreads();
    {   // one thread per point; ascending cc keeps lowest center index on ties
        float bv = rv[0][tid];
        int bi = ri[0][tid];
#pragma unroll
        for (int g = 1; g < 8; ++g) {
            float v = rv[g][tid];
            if (v < bv) { bv = v; bi = ri[g][tid]; }
        }
        g_labels[r * NP + pbase + tid] = bi;
    }
}

// ------------- deterministic counting sort: CSR member lists ---------
__global__ __launch_bounds__(512) void build_lists_kernel() {
    __shared__ int lab[NP];
    __shared__ int cnt[64][8];
    __shared__ int ctot[64];
    int r = blockIdx.x, tid = threadIdx.x;
    for (int i = tid; i < NP; i += 512) lab[i] = g_labels[r * NP + i];
    __syncthreads();
    int c = tid & 63, ch = tid >> 6;
    int base = ch * 512;
    int n0 = 0;
#pragma unroll 8
    for (int i = 0; i < 512; ++i) n0 += (lab[base + i] == c);
    cnt[c][ch] = n0;
    __syncthreads();
    if (ch == 0) {
        int t = 0;
#pragma unroll
        for (int k = 0; k < 8; k++) t += cnt[c][k];
        g_counts[r * 64 + c] = t;
        ctot[c] = t;
    }
    __syncthreads();
    int coff = 0;
    for (int k = 0; k < c; ++k) coff += ctot[k];
    if (ch == 0) g_offsets[r * 64 + c] = coff;
    int pos = coff;
    for (int k = 0; k < ch; k++) pos += cnt[c][k];
    int *dst = &g_members[r * NP];
    for (int i = 0; i < 512; ++i) {
        int n = base + i;
        if (lab[n] == c) dst[pos++] = n;
    }
}

// ------- sums over members (ascending n, bit-identical chains) + finalize ----
__global__ __launch_bounds__(256) void sum_finalize_kernel(const float *__restrict__ x) {
    __shared__ int mem[NP];
    __shared__ float s[SD];
    int b = blockIdx.x;              // r*64 + l
    int r = b >> 6, tid = threadIdx.x;
    int cnt = g_counts[b];
    int off = g_offsets[b];
    size_t cbase = ((size_t)b) << 10;
    for (int i = tid; i < cnt; i += 256) mem[i] = g_members[r * NP + off + i];
    __syncthreads();

    float ax = 0.f, ay = 0.f, az = 0.f, aw = 0.f;
    const float *xr = x + ((size_t)r * NP) * SD;
    int d = tid * 4;
#pragma unroll 4
    for (int m = 0; m < cnt; ++m) {
        float4 v = *(const float4 *)(xr + ((size_t)mem[m]) * SD + d);
        ax = __fadd_rn(ax, v.x); ay = __fadd_rn(ay, v.y);
        az = __fadd_rn(az, v.z); aw = __fadd_rn(aw, v.w);
    }
    float fcnt = (float)cnt;
    float o0, o1, o2, o3;
    if (cnt > 0) {
        o0 = __fdiv_rn(ax, fcnt); o1 = __fdiv_rn(ay, fcnt);
        o2 = __fdiv_rn(az, fcnt); o3 = __fdiv_rn(aw, fcnt);
    } else {
        o0 = g_centers[cbase + d + 0]; o1 = g_centers[cbase + d + 1];
        o2 = g_centers[cbase + d + 2]; o3 = g_centers[cbase + d + 3];
    }
    g_centers[cbase + d + 0] = o0; g_centers[cbase + d + 1] = o1;
    g_centers[cbase + d + 2] = o2; g_centers[cbase + d + 3] = o3;
    s[d + 0] = o0; s[d + 1] = o1; s[d + 2] = o2; s[d + 3] = o3;
    __syncthreads();
    if (tid == 0) {
        float ss = 0.f;
#pragma unroll 8
        for (int dd = 0; dd < SD; ++dd) ss = __fadd_rn(ss, __fmul_rn(s[dd], s[dd]));
        g_c2[b] = ss;
    }
}

// out[r,n,:] = centers[r, labels[r,n], :]
__global__ __launch_bounds__(256) void output_kernel(float *__restrict__ out) {
    int b = blockIdx.x;
    int lab = g_labels[b];
    int r = b >> 12;
    const float4 *src = (const float4 *)(g_centers + (((size_t)(r * 64 + lab)) << 10));
    float4 *dst = (float4 *)(out + ((size_t)b << 10));
    dst[threadIdx.x] = src[threadIdx.x];
}

extern "C" void kernel_launch(void* const* d_in, const int* in_sizes, int n_in,
                              void* d_out, int out_size) {
    const float *x = (const float *)d_in[0];
    float *out = (float *)d_out;
    (void)in_sizes; (void)n_in; (void)out_size;

    init_kernel<<<RG, 1024>>>();
    x2_kernel<<<RG * NP / 8, 128>>>(x);
    gather_init_kernel<<<RG * LC, 128>>>(x);
    for (int it = 0; it < 10; ++it) {
        assign_kernel<<<RG * 16, 256>>>(x);
        build_lists_kernel<<<RG, 512>>>();
        sum_finalize_kernel<<<RG * LC, 256>>>(x);
    }
    assign_kernel<<<RG * 16, 256>>>(x);
    output_kernel<<<RG * NP, 256>>>(out);
}

// round 8
// speedup vs baseline: 2.1625x; 1.1893x over previous
#include <cuda_runtime.h>

#define RG 8
#define LC 64
#define NP 4096
#define SD 1024

// ---------------- device scratch ----------------
__device__ float g_centers[RG * LC * SD];
__device__ float g_c2[RG * LC];
__device__ float g_x2[RG * NP];
__device__ int   g_labels[RG * NP];
__device__ int   g_init_idx[RG * LC];

// ---------------- f32x2 helpers (each lane = independent IEEE rn fp32) ------
__device__ __forceinline__ unsigned long long fma2(unsigned long long a,
                                                   unsigned long long b,
                                                   unsigned long long c) {
    unsigned long long d;
    asm("fma.rn.f32x2 %0, %1, %2, %3;" : "=l"(d) : "l"(a), "l"(b), "l"(c));
    return d;
}
__device__ __forceinline__ void unpack2(unsigned long long v, float &lo, float &hi) {
    asm("mov.b64 {%0, %1}, %2;" : "=f"(lo), "=f"(hi) : "l"(v));
}

// ---------------- threefry2x32 (20 rounds) ----------------
__device__ __forceinline__ unsigned rotl32(unsigned v, int s) {
    return (v << s) | (v >> (32 - s));
}
__device__ __forceinline__ void threefry2x32(unsigned k0, unsigned k1,
                                             unsigned &x0, unsigned &x1) {
    unsigned ks0 = k0, ks1 = k1, ks2 = k0 ^ k1 ^ 0x1BD11BDAu;
    x0 += ks0; x1 += ks1;
#define TF_R(r) { x0 += x1; x1 = rotl32(x1, (r)); x1 ^= x0; }
    TF_R(13) TF_R(15) TF_R(26) TF_R(6)   x0 += ks1; x1 += ks2 + 1u;
    TF_R(17) TF_R(29) TF_R(16) TF_R(24)  x0 += ks2; x1 += ks0 + 2u;
    TF_R(13) TF_R(15) TF_R(26) TF_R(6)   x0 += ks0; x1 += ks1 + 3u;
    TF_R(17) TF_R(29) TF_R(16) TF_R(24)  x0 += ks1; x1 += ks2 + 4u;
    TF_R(13) TF_R(15) TF_R(26) TF_R(6)   x0 += ks2; x1 += ks0 + 5u;
#undef TF_R
}

__device__ void bitonic4096(unsigned long long *kc, int tid) {
    for (int k = 2; k <= 4096; k <<= 1) {
        for (int j = k >> 1; j > 0; j >>= 1) {
            for (int t = tid; t < 4096; t += 1024) {
                int ixj = t ^ j;
                if (ixj > t) {
                    unsigned long long a = kc[t], b = kc[ixj];
                    bool up = ((t & k) == 0);
                    if ((a > b) == up) { kc[t] = b; kc[ixj] = a; }
                }
            }
            __syncthreads();
        }
    }
}

// reproduce jax.random.permutation(split(key(42),8)[r], 4096)[:64]
__global__ __launch_bounds__(1024) void init_kernel() {
    __shared__ unsigned long long kc[4096];
    __shared__ unsigned perm1[4096];
    int r = blockIdx.x, tid = threadIdx.x;

    unsigned K0 = 0u, K1 = (unsigned)r;
    threefry2x32(0u, 42u, K0, K1);
    unsigned n0 = 0u, n1 = 0u;   threefry2x32(K0, K1, n0, n1);
    unsigned s1a = 0u, s1b = 1u; threefry2x32(K0, K1, s1a, s1b);
    unsigned s2a = 0u, s2b = 1u; threefry2x32(n0, n1, s2a, s2b);

    for (int i = tid; i < 4096; i += 1024) {
        unsigned a = 0u, b = (unsigned)i;
        threefry2x32(s1a, s1b, a, b);
        kc[i] = ((unsigned long long)(a ^ b) << 32) | (unsigned)i;
    }
    __syncthreads();
    bitonic4096(kc, tid);
    for (int i = tid; i < 4096; i += 1024)
        perm1[i] = (unsigned)(kc[i] & 0xffffffffu);
    __syncthreads();

    for (int i = tid; i < 4096; i += 1024) {
        unsigned a = 0u, b = (unsigned)i;
        threefry2x32(s2a, s2b, a, b);
        kc[i] = ((unsigned long long)(a ^ b) << 32) | (unsigned)i;
    }
    __syncthreads();
    bitonic4096(kc, tid);
    if (tid < 64)
        g_init_idx[r * 64 + tid] = (int)perm1[(unsigned)(kc[tid] & 0xffffffffu)];
}

// ---------------- x2: 8 parallel flat-sequential chains per block ----------------
#define X2ROW 1036
__global__ __launch_bounds__(128) void x2_kernel(const float *__restrict__ x) {
    __shared__ __align__(16) float s[8 * X2ROW];
    int pb = blockIdx.x * 8;
    const float4 *src = (const float4 *)(x + (size_t)pb * SD);
    for (int i = threadIdx.x; i < 8 * (SD / 4); i += 128) {
        int p = i >> 8, q = i & 255;
        *(float4 *)&s[p * X2ROW + q * 4] = src[p * 256 + q];
    }
    __syncthreads();
    if (threadIdx.x < 8) {
        const float *row = &s[threadIdx.x * X2ROW];
        float ss = 0.f;
#pragma unroll 8
        for (int d = 0; d < SD; ++d)
            ss = __fadd_rn(ss, __fmul_rn(row[d], row[d]));
        g_x2[pb + threadIdx.x] = ss;
    }
}

// centers[r][l] = pts[r][init_idx]; fused flat-sequential c2
__global__ __launch_bounds__(128) void gather_init_kernel(const float *__restrict__ x) {
    __shared__ float s[SD];
    int b = blockIdx.x, r = b >> 6, tid = threadIdx.x;
    int idx = g_init_idx[b];
    const float *src = x + ((size_t)(r * NP + idx)) * SD;
    size_t base = ((size_t)b) << 10;
    for (int d = tid; d < SD; d += 128) {
        float v = src[d];
        g_centers[base + d] = v;
        s[d] = v;
    }
    __syncthreads();
    if (tid == 0) {
        float ss = 0.f;
#pragma unroll 8
        for (int d = 0; d < SD; ++d) ss = __fadd_rn(ss, __fmul_rn(s[d], s[d]));
        g_c2[b] = ss;
    }
}

// ---------------- assign: argmin_l fl(fl(x2+c2[l]) - 2*dot) ----------------
// 512 threads; block = 256 pts x 64 ctrs; thread tile 4pt(2 f32x2 pairs) x 8ctr.
// Centers pre-duplicated (c,c) in smem -> broadcast LDS.128, zero packs.
// Dot = single fma chain, strictly ascending k. write_out: fused final gather.
#define KCH 8
#define BPT 256
__global__ __launch_bounds__(512) void assign_kernel(const float *__restrict__ x,
                                                     float *__restrict__ out,
                                                     int write_out) {
    __shared__ __align__(16) float pT[2][KCH][BPT];    // 16 KB
    __shared__ __align__(16) float cTd[2][KCH][128];   // 8 KB
    __shared__ float rv[8][BPT];                       // 8 KB
    __shared__ int   ri[8][BPT];                       // 8 KB

    int bx = blockIdx.x;
    int r = bx >> 4, tile = bx & 15;
    int pbase = tile * BPT;
    const float *pts = x + ((size_t)r * NP) * SD;
    const float *ctr = g_centers + ((size_t)r * LC) * SD;
    int tid = threadIdx.x;
    int pc = tid & 63;          // 64 point groups of 4
    int cc = tid >> 6;          // 8 center groups of 8

    bool pload = tid < 256;
    bool cload = (tid >= 256) && (tid < 384);
    int ci = tid - 256;
    int sc_c = ci & 63, sc_h = (ci >> 6) & 1;
    const float *prow = pts + (size_t)(pbase + (pload ? tid : 0)) * SD;
    const float *crow = ctr + (size_t)(cload ? sc_c : 0) * SD + sc_h * 4;

    unsigned long long acc[2][8];
#pragma unroll
    for (int i = 0; i < 2; i++)
#pragma unroll
        for (int j = 0; j < 8; j++) acc[i][j] = 0ull;

    float4 sp0, sp1, sc;
    if (pload) { sp0 = *(const float4 *)(prow); sp1 = *(const float4 *)(prow + 4); }
    if (cload) sc = *(const float4 *)(crow);
    if (pload) {
        pT[0][0][tid] = sp0.x; pT[0][1][tid] = sp0.y;
        pT[0][2][tid] = sp0.z; pT[0][3][tid] = sp0.w;
        pT[0][4][tid] = sp1.x; pT[0][5][tid] = sp1.y;
        pT[0][6][tid] = sp1.z; pT[0][7][tid] = sp1.w;
    }
    if (cload) {
        int kb = sc_h * 4, c2i = sc_c * 2;
        cTd[0][kb + 0][c2i] = sc.x; cTd[0][kb + 0][c2i + 1] = sc.x;
        cTd[0][kb + 1][c2i] = sc.y; cTd[0][kb + 1][c2i + 1] = sc.y;
        cTd[0][kb + 2][c2i] = sc.z; cTd[0][kb + 2][c2i + 1] = sc.z;
        cTd[0][kb + 3][c2i] = sc.w; cTd[0][kb + 3][c2i + 1] = sc.w;
    }
    if (pload) { sp0 = *(const float4 *)(prow + KCH); sp1 = *(const float4 *)(prow + KCH + 4); }
    if (cload) sc = *(const float4 *)(crow + KCH);
    __syncthreads();

    const int NCHUNK = SD / KCH;   // 128
    for (int c = 0; c < NCHUNK; ++c) {
        int cur = c & 1;
        if (c + 1 < NCHUNK) {
            int nb = cur ^ 1;
            if (pload) {
                pT[nb][0][tid] = sp0.x; pT[nb][1][tid] = sp0.y;
                pT[nb][2][tid] = sp0.z; pT[nb][3][tid] = sp0.w;
                pT[nb][4][tid] = sp1.x; pT[nb][5][tid] = sp1.y;
                pT[nb][6][tid] = sp1.z; pT[nb][7][tid] = sp1.w;
            }
            if (cload) {
                int kb = sc_h * 4, c2i = sc_c * 2;
                cTd[nb][kb + 0][c2i] = sc.x; cTd[nb][kb + 0][c2i + 1] = sc.x;
                cTd[nb][kb + 1][c2i] = sc.y; cTd[nb][kb + 1][c2i + 1] = sc.y;
                cTd[nb][kb + 2][c2i] = sc.z; cTd[nb][kb + 2][c2i + 1] = sc.z;
                cTd[nb][kb + 3][c2i] = sc.w; cTd[nb][kb + 3][c2i + 1] = sc.w;
            }
            if (c + 2 < NCHUNK) {
                int k0 = (c + 2) * KCH;
                if (pload) {
                    sp0 = *(const float4 *)(prow + k0);
                    sp1 = *(const float4 *)(prow + k0 + 4);
                }
                if (cload) sc = *(const float4 *)(crow + k0);
            }
        }
#pragma unroll
        for (int kk = 0; kk < KCH; ++kk) {
            ulonglong2 pa  = *(const ulonglong2 *)&pT[cur][kk][pc * 4];
            ulonglong2 c01 = *(const ulonglong2 *)&cTd[cur][kk][cc * 16 + 0];
            ulonglong2 c23 = *(const ulonglong2 *)&cTd[cur][kk][cc * 16 + 4];
            ulonglong2 c45 = *(const ulonglong2 *)&cTd[cur][kk][cc * 16 + 8];
            ulonglong2 c67 = *(const ulonglong2 *)&cTd[cur][kk][cc * 16 + 12];
            unsigned long long pp[2] = {pa.x, pa.y};
            unsigned long long cd[8] = {c01.x, c01.y, c23.x, c23.y,
                                        c45.x, c45.y, c67.x, c67.y};
#pragma unroll
            for (int i = 0; i < 2; i++)
#pragma unroll
                for (int j = 0; j < 8; j++)
                    acc[i][j] = fma2(pp[i], cd[j], acc[i][j]);
        }
        __syncthreads();
    }

    float c2s[8];
#pragma unroll
    for (int j = 0; j < 8; j++) c2s[j] = g_c2[r * 64 + cc * 8 + j];
#pragma unroll
    for (int e = 0; e < 4; ++e) {
        int pair = e >> 1, lane = e & 1;
        int p = pc * 4 + e;
        float x2v = g_x2[r * NP + pbase + p];
        float dots[8];
#pragma unroll
        for (int j = 0; j < 8; j++) {
            float lo, hi;
            unpack2(acc[pair][j], lo, hi);
            dots[j] = lane ? hi : lo;
        }
        float bv;
        int bj = 0;
        {
            float sS = __fadd_rn(x2v, c2s[0]);
            bv = __fadd_rn(sS, __fmul_rn(-2.f, dots[0]));
        }
#pragma unroll
        for (int j = 1; j < 8; j++) {
            float sS = __fadd_rn(x2v, c2s[j]);
            float v = __fadd_rn(sS, __fmul_rn(-2.f, dots[j]));
            if (v < bv) { bv = v; bj = j; }   // strict < keeps first-min
        }
        rv[cc][p] = bv;
        ri[cc][p] = cc * 8 + bj;
    }
    __syncthreads();
    if (tid < 256) {   // ascending cc keeps lowest center index on ties
        float bv = rv[0][tid];
        int bi = ri[0][tid];
#pragma unroll
        for (int g = 1; g < 8; ++g) {
            float v = rv[g][tid];
            if (v < bv) { bv = v; bi = ri[g][tid]; }
        }
        g_labels[r * NP + pbase + tid] = bi;
        ri[0][tid] = bi;   // stash for fused output
    }
    if (write_out) {
        __syncthreads();
        int w = tid >> 5, lane = tid & 31;
#pragma unroll
        for (int i = 0; i < 16; ++i) {
            int row = w * 16 + i;
            int lb = ri[0][row];
            const float4 *src = (const float4 *)(g_centers + (((size_t)(r * 64 + lb)) << 10));
            float4 *dst = (float4 *)(out + (((size_t)(r * NP + pbase + row)) << 10));
#pragma unroll
            for (int j = 0; j < 8; ++j)
                dst[lane + 32 * j] = src[lane + 32 * j];
        }
    }
}

// -------- fused update: per-cluster stable compaction + sums + finalize --------
// block = (r, cluster c). Member order: thread chunks of 16 ascending -> exact
// ascending-n, identical chains to the passing version.
__global__ __launch_bounds__(256) void update_kernel(const float *__restrict__ x) {
    __shared__ int   lab[NP];     // 16 KB
    __shared__ int   mem[NP];     // 16 KB (worst case one cluster owns all)
    __shared__ int   cntT[256];
    __shared__ float s[SD];       // 4 KB
    int b = blockIdx.x;           // r*64 + c
    int r = b >> 6, c = b & 63, tid = threadIdx.x;

    const int4 *lsrc = (const int4 *)&g_labels[r * NP];
    for (int i = tid; i < NP / 4; i += 256) ((int4 *)lab)[i] = lsrc[i];
    __syncthreads();

    int base = tid * 16, k = 0;
#pragma unroll
    for (int i = 0; i < 16; ++i) k += (lab[base + i] == c);
    cntT[tid] = k;
    __syncthreads();
    int pre = 0, tot = 0;
    for (int i = 0; i < 256; ++i) {       // smem broadcast loop
        int v = cntT[i];
        if (i < tid) pre += v;
        tot += v;
    }
    int pos = pre;
#pragma unroll
    for (int i = 0; i < 16; ++i) {
        int n = base + i;
        if (lab[n] == c) mem[pos++] = n;
    }
    __syncthreads();

    int cnt = tot;
    size_t cbase = ((size_t)b) << 10;
    float ax = 0.f, ay = 0.f, az = 0.f, aw = 0.f;
    const float *xr = x + ((size_t)r * NP) * SD;
    int d = tid * 4;
#pragma unroll 8
    for (int m = 0; m < cnt; ++m) {
        float4 v = *(const float4 *)(xr + ((size_t)mem[m]) * SD + d);
        ax = __fadd_rn(ax, v.x); ay = __fadd_rn(ay, v.y);
        az = __fadd_rn(az, v.z); aw = __fadd_rn(aw, v.w);
    }
    float fcnt = (float)cnt;
    float o0, o1, o2, o3;
    if (cnt > 0) {
        o0 = __fdiv_rn(ax, fcnt); o1 = __fdiv_rn(ay, fcnt);
        o2 = __fdiv_rn(az, fcnt); o3 = __fdiv_rn(aw, fcnt);
    } else {
        o0 = g_centers[cbase + d + 0]; o1 = g_centers[cbase + d + 1];
        o2 = g_centers[cbase + d + 2]; o3 = g_centers[cbase + d + 3];
    }
    g_centers[cbase + d + 0] = o0; g_centers[cbase + d + 1] = o1;
    g_centers[cbase + d + 2] = o2; g_centers[cbase + d + 3] = o3;
    s[d + 0] = o0; s[d + 1] = o1; s[d + 2] = o2; s[d + 3] = o3;
    __syncthreads();
    if (tid == 0) {
        float ss = 0.f;
#pragma unroll 8
        for (int dd = 0; dd < SD; ++dd) ss = __fadd_rn(ss, __fmul_rn(s[dd], s[dd]));
        g_c2[b] = ss;
    }
}

extern "C" void kernel_launch(void* const* d_in, const int* in_sizes, int n_in,
                              void* d_out, int out_size) {
    const float *x = (const float *)d_in[0];
    float *out = (float *)d_out;
    (void)in_sizes; (void)n_in; (void)out_size;

    init_kernel<<<RG, 1024>>>();
    x2_kernel<<<RG * NP / 8, 128>>>(x);
    gather_init_kernel<<<RG * LC, 128>>>(x);
    for (int it = 0; it < 10; ++it) {
        assign_kernel<<<RG * 16, 512>>>(x, out, 0);
        update_kernel<<<RG * LC, 256>>>(x);
    }
    assign_kernel<<<RG * 16, 512>>>(x, out, 1);
}

// round 9
// speedup vs baseline: 2.2206x; 1.0269x over previous
#include <cuda_runtime.h>

#define RG 8
#define LC 64
#define NP 4096
#define SD 1024

// ---------------- device scratch ----------------
__device__ float g_centers[RG * LC * SD];
__device__ float g_c2[RG * LC];
__device__ float g_x2[RG * NP];
__device__ int   g_labels[RG * NP];
__device__ int   g_init_idx[RG * LC];

// ---------------- f32x2 helpers (each lane = independent IEEE rn fp32) ------
__device__ __forceinline__ unsigned long long fma2(unsigned long long a,
                                                   unsigned long long b,
                                                   unsigned long long c) {
    unsigned long long d;
    asm("fma.rn.f32x2 %0, %1, %2, %3;" : "=l"(d) : "l"(a), "l"(b), "l"(c));
    return d;
}
__device__ __forceinline__ void unpack2(unsigned long long v, float &lo, float &hi) {
    asm("mov.b64 {%0, %1}, %2;" : "=f"(lo), "=f"(hi) : "l"(v));
}

// ---------------- threefry2x32 (20 rounds) ----------------
__device__ __forceinline__ unsigned rotl32(unsigned v, int s) {
    return (v << s) | (v >> (32 - s));
}
__device__ __forceinline__ void threefry2x32(unsigned k0, unsigned k1,
                                             unsigned &x0, unsigned &x1) {
    unsigned ks0 = k0, ks1 = k1, ks2 = k0 ^ k1 ^ 0x1BD11BDAu;
    x0 += ks0; x1 += ks1;
#define TF_R(r) { x0 += x1; x1 = rotl32(x1, (r)); x1 ^= x0; }
    TF_R(13) TF_R(15) TF_R(26) TF_R(6)   x0 += ks1; x1 += ks2 + 1u;
    TF_R(17) TF_R(29) TF_R(16) TF_R(24)  x0 += ks2; x1 += ks0 + 2u;
    TF_R(13) TF_R(15) TF_R(26) TF_R(6)   x0 += ks0; x1 += ks1 + 3u;
    TF_R(17) TF_R(29) TF_R(16) TF_R(24)  x0 += ks1; x1 += ks2 + 4u;
    TF_R(13) TF_R(15) TF_R(26) TF_R(6)   x0 += ks2; x1 += ks0 + 5u;
#undef TF_R
}

__device__ void bitonic4096(unsigned long long *kc, int tid) {
    for (int k = 2; k <= 4096; k <<= 1) {
        for (int j = k >> 1; j > 0; j >>= 1) {
            for (int t = tid; t < 4096; t += 1024) {
                int ixj = t ^ j;
                if (ixj > t) {
                    unsigned long long a = kc[t], b = kc[ixj];
                    bool up = ((t & k) == 0);
                    if ((a > b) == up) { kc[t] = b; kc[ixj] = a; }
                }
            }
            __syncthreads();
        }
    }
}

// reproduce jax.random.permutation(split(key(42),8)[r], 4096)[:64]
__global__ __launch_bounds__(1024) void init_kernel() {
    __shared__ unsigned long long kc[4096];
    __shared__ unsigned perm1[4096];
    int r = blockIdx.x, tid = threadIdx.x;

    unsigned K0 = 0u, K1 = (unsigned)r;
    threefry2x32(0u, 42u, K0, K1);
    unsigned n0 = 0u, n1 = 0u;   threefry2x32(K0, K1, n0, n1);
    unsigned s1a = 0u, s1b = 1u; threefry2x32(K0, K1, s1a, s1b);
    unsigned s2a = 0u, s2b = 1u; threefry2x32(n0, n1, s2a, s2b);

    for (int i = tid; i < 4096; i += 1024) {
        unsigned a = 0u, b = (unsigned)i;
        threefry2x32(s1a, s1b, a, b);
        kc[i] = ((unsigned long long)(a ^ b) << 32) | (unsigned)i;
    }
    __syncthreads();
    bitonic4096(kc, tid);
    for (int i = tid; i < 4096; i += 1024)
        perm1[i] = (unsigned)(kc[i] & 0xffffffffu);
    __syncthreads();

    for (int i = tid; i < 4096; i += 1024) {
        unsigned a = 0u, b = (unsigned)i;
        threefry2x32(s2a, s2b, a, b);
        kc[i] = ((unsigned long long)(a ^ b) << 32) | (unsigned)i;
    }
    __syncthreads();
    bitonic4096(kc, tid);
    if (tid < 64)
        g_init_idx[r * 64 + tid] = (int)perm1[(unsigned)(kc[tid] & 0xffffffffu)];
}

// nop: shifts ncu's -s 5 capture onto update_kernel
__global__ void nop_kernel() {}

// ---------------- x2: 8 parallel flat-sequential chains per block ----------------
#define X2ROW 1036
__global__ __launch_bounds__(128) void x2_kernel(const float *__restrict__ x) {
    __shared__ __align__(16) float s[8 * X2ROW];
    int pb = blockIdx.x * 8;
    const float4 *src = (const float4 *)(x + (size_t)pb * SD);
    for (int i = threadIdx.x; i < 8 * (SD / 4); i += 128) {
        int p = i >> 8, q = i & 255;
        *(float4 *)&s[p * X2ROW + q * 4] = src[p * 256 + q];
    }
    __syncthreads();
    if (threadIdx.x < 8) {
        const float *row = &s[threadIdx.x * X2ROW];
        float ss = 0.f;
#pragma unroll 8
        for (int d = 0; d < SD; ++d)
            ss = __fadd_rn(ss, __fmul_rn(row[d], row[d]));
        g_x2[pb + threadIdx.x] = ss;
    }
}

// centers[r][l] = pts[r][init_idx]; fused flat-sequential c2
__global__ __launch_bounds__(128) void gather_init_kernel(const float *__restrict__ x) {
    __shared__ float s[SD];
    int b = blockIdx.x, r = b >> 6, tid = threadIdx.x;
    int idx = g_init_idx[b];
    const float *src = x + ((size_t)(r * NP + idx)) * SD;
    size_t base = ((size_t)b) << 10;
    for (int d = tid; d < SD; d += 128) {
        float v = src[d];
        g_centers[base + d] = v;
        s[d] = v;
    }
    __syncthreads();
    if (tid == 0) {
        float ss = 0.f;
#pragma unroll 8
        for (int d = 0; d < SD; ++d) ss = __fadd_rn(ss, __fmul_rn(s[d], s[d]));
        g_c2[b] = ss;
    }
}

// ---------------- assign: argmin_l fl(fl(x2+c2[l]) - 2*dot) ----------------
// 512 threads; block = 256 pts x 64 ctrs; thread tile 4pt(2 f32x2 pairs) x 8ctr.
// Centers pre-duplicated (c,c) in smem; KCH=16 (64 barriers/launch).
// Dot = single fma chain, strictly ascending k.
#define KCH 16
#define BPT 256
__global__ __launch_bounds__(512) void assign_kernel(const float *__restrict__ x,
                                                     float *__restrict__ out,
                                                     int write_out) {
    __shared__ __align__(16) float pT[2][KCH][BPT];    // 32 KB
    __shared__ __align__(16) float cTd[2][KCH][128];   // 16 KB
    __shared__ float rv[8][BPT];                       // 8 KB
    __shared__ int   ri[8][BPT];                       // 8 KB

    int bx = blockIdx.x;
    int r = bx >> 4, tile = bx & 15;
    int pbase = tile * BPT;
    const float *pts = x + ((size_t)r * NP) * SD;
    const float *ctr = g_centers + ((size_t)r * LC) * SD;
    int tid = threadIdx.x;
    int pc = tid & 63;          // 64 point groups of 4
    int cc = tid >> 6;          // 8 center groups of 8

    bool pload = tid < 256;
    bool cload = (tid >= 256) && (tid < 384);
    int ci = tid - 256;
    int sc_c = ci & 63, sc_h = (ci >> 6) & 1;          // center, k-half (8 each)
    const float *prow = pts + (size_t)(pbase + (pload ? tid : 0)) * SD;
    const float *crow = ctr + (size_t)(cload ? sc_c : 0) * SD + sc_h * 8;

    unsigned long long acc[2][8];
#pragma unroll
    for (int i = 0; i < 2; i++)
#pragma unroll
        for (int j = 0; j < 8; j++) acc[i][j] = 0ull;

    float4 sp[4], sc0, sc1;
    // load chunk 0
    if (pload) {
#pragma unroll
        for (int q = 0; q < 4; q++) sp[q] = *(const float4 *)(prow + q * 4);
    }
    if (cload) { sc0 = *(const float4 *)(crow); sc1 = *(const float4 *)(crow + 4); }
    // store chunk 0 -> buf 0
    if (pload) {
#pragma unroll
        for (int q = 0; q < 4; q++) {
            pT[0][q * 4 + 0][tid] = sp[q].x; pT[0][q * 4 + 1][tid] = sp[q].y;
            pT[0][q * 4 + 2][tid] = sp[q].z; pT[0][q * 4 + 3][tid] = sp[q].w;
        }
    }
    if (cload) {
        int kb = sc_h * 8, c2i = sc_c * 2;
        cTd[0][kb + 0][c2i] = sc0.x; cTd[0][kb + 0][c2i + 1] = sc0.x;
        cTd[0][kb + 1][c2i] = sc0.y; cTd[0][kb + 1][c2i + 1] = sc0.y;
        cTd[0][kb + 2][c2i] = sc0.z; cTd[0][kb + 2][c2i + 1] = sc0.z;
        cTd[0][kb + 3][c2i] = sc0.w; cTd[0][kb + 3][c2i + 1] = sc0.w;
        cTd[0][kb + 4][c2i] = sc1.x; cTd[0][kb + 4][c2i + 1] = sc1.x;
        cTd[0][kb + 5][c2i] = sc1.y; cTd[0][kb + 5][c2i + 1] = sc1.y;
        cTd[0][kb + 6][c2i] = sc1.z; cTd[0][kb + 6][c2i + 1] = sc1.z;
        cTd[0][kb + 7][c2i] = sc1.w; cTd[0][kb + 7][c2i + 1] = sc1.w;
    }
    // preload chunk 1
    if (pload) {
#pragma unroll
        for (int q = 0; q < 4; q++) sp[q] = *(const float4 *)(prow + KCH + q * 4);
    }
    if (cload) { sc0 = *(const float4 *)(crow + KCH); sc1 = *(const float4 *)(crow + KCH + 4); }
    __syncthreads();

    const int NCHUNK = SD / KCH;   // 64
    for (int c = 0; c < NCHUNK; ++c) {
        int cur = c & 1;
        if (c + 1 < NCHUNK) {
            int nb = cur ^ 1;
            if (pload) {
#pragma unroll
                for (int q = 0; q < 4; q++) {
                    pT[nb][q * 4 + 0][tid] = sp[q].x; pT[nb][q * 4 + 1][tid] = sp[q].y;
                    pT[nb][q * 4 + 2][tid] = sp[q].z; pT[nb][q * 4 + 3][tid] = sp[q].w;
                }
            }
            if (cload) {
                int kb = sc_h * 8, c2i = sc_c * 2;
                cTd[nb][kb + 0][c2i] = sc0.x; cTd[nb][kb + 0][c2i + 1] = sc0.x;
                cTd[nb][kb + 1][c2i] = sc0.y; cTd[nb][kb + 1][c2i + 1] = sc0.y;
                cTd[nb][kb + 2][c2i] = sc0.z; cTd[nb][kb + 2][c2i + 1] = sc0.z;
                cTd[nb][kb + 3][c2i] = sc0.w; cTd[nb][kb + 3][c2i + 1] = sc0.w;
                cTd[nb][kb + 4][c2i] = sc1.x; cTd[nb][kb + 4][c2i + 1] = sc1.x;
                cTd[nb][kb + 5][c2i] = sc1.y; cTd[nb][kb + 5][c2i + 1] = sc1.y;
                cTd[nb][kb + 6][c2i] = sc1.z; cTd[nb][kb + 6][c2i + 1] = sc1.z;
                cTd[nb][kb + 7][c2i] = sc1.w; cTd[nb][kb + 7][c2i + 1] = sc1.w;
            }
            if (c + 2 < NCHUNK) {
                int k0 = (c + 2) * KCH;
                if (pload) {
#pragma unroll
                    for (int q = 0; q < 4; q++)
                        sp[q] = *(const float4 *)(prow + k0 + q * 4);
                }
                if (cload) {
                    sc0 = *(const float4 *)(crow + k0);
                    sc1 = *(const float4 *)(crow + k0 + 4);
                }
            }
        }
#pragma unroll
        for (int kk = 0; kk < KCH; ++kk) {
            ulonglong2 pa  = *(const ulonglong2 *)&pT[cur][kk][pc * 4];
            ulonglong2 c01 = *(const ulonglong2 *)&cTd[cur][kk][cc * 16 + 0];
            ulonglong2 c23 = *(const ulonglong2 *)&cTd[cur][kk][cc * 16 + 4];
            ulonglong2 c45 = *(const ulonglong2 *)&cTd[cur][kk][cc * 16 + 8];
            ulonglong2 c67 = *(const ulonglong2 *)&cTd[cur][kk][cc * 16 + 12];
            unsigned long long pp[2] = {pa.x, pa.y};
            unsigned long long cd[8] = {c01.x, c01.y, c23.x, c23.y,
                                        c45.x, c45.y, c67.x, c67.y};
#pragma unroll
            for (int i = 0; i < 2; i++)
#pragma unroll
                for (int j = 0; j < 8; j++)
                    acc[i][j] = fma2(pp[i], cd[j], acc[i][j]);
        }
        __syncthreads();
    }

    float c2s[8];
#pragma unroll
    for (int j = 0; j < 8; j++) c2s[j] = g_c2[r * 64 + cc * 8 + j];
#pragma unroll
    for (int e = 0; e < 4; ++e) {
        int pair = e >> 1, lane = e & 1;
        int p = pc * 4 + e;
        float x2v = g_x2[r * NP + pbase + p];
        float dots[8];
#pragma unroll
        for (int j = 0; j < 8; j++) {
            float lo, hi;
            unpack2(acc[pair][j], lo, hi);
            dots[j] = lane ? hi : lo;
        }
        float bv;
        int bj = 0;
        {
            float sS = __fadd_rn(x2v, c2s[0]);
            bv = __fadd_rn(sS, __fmul_rn(-2.f, dots[0]));
        }
#pragma unroll
        for (int j = 1; j < 8; j++) {
            float sS = __fadd_rn(x2v, c2s[j]);
            float v = __fadd_rn(sS, __fmul_rn(-2.f, dots[j]));
            if (v < bv) { bv = v; bj = j; }   // strict < keeps first-min
        }
        rv[cc][p] = bv;
        ri[cc][p] = cc * 8 + bj;
    }
    __syncthreads();
    if (tid < 256) {   // ascending cc keeps lowest center index on ties
        float bv = rv[0][tid];
        int bi = ri[0][tid];
#pragma unroll
        for (int g = 1; g < 8; ++g) {
            float v = rv[g][tid];
            if (v < bv) { bv = v; bi = ri[g][tid]; }
        }
        g_labels[r * NP + pbase + tid] = bi;
        ri[0][tid] = bi;   // stash for fused output
    }
    if (write_out) {
        __syncthreads();
        int w = tid >> 5, lane = tid & 31;
#pragma unroll
        for (int i = 0; i < 16; ++i) {
            int row = w * 16 + i;
            int lb = ri[0][row];
            const float4 *src = (const float4 *)(g_centers + (((size_t)(r * 64 + lb)) << 10));
            float4 *dst = (float4 *)(out + (((size_t)(r * NP + pbase + row)) << 10));
#pragma unroll
            for (int j = 0; j < 8; ++j)
                dst[lane + 32 * j] = src[lane + 32 * j];
        }
    }
}

// -------- fused update: per-cluster stable compaction + sums + finalize --------
// block = (r, cluster c); 512 threads, 2 dims each (float2).
// Member order: thread chunks of 8 ascending -> exact ascending-n.
__global__ __launch_bounds__(512) void update_kernel(const float *__restrict__ x) {
    __shared__ int   lab[NP];     // 16 KB
    __shared__ int   mem[NP];     // 16 KB
    __shared__ int   cntT[512];
    __shared__ float s[SD];       // 4 KB
    int b = blockIdx.x;           // r*64 + c
    int r = b >> 6, c = b & 63, tid = threadIdx.x;

    const int4 *lsrc = (const int4 *)&g_labels[r * NP];
    for (int i = tid; i < NP / 4; i += 512) ((int4 *)lab)[i] = lsrc[i];
    __syncthreads();

    int base = tid * 8, k = 0;
#pragma unroll
    for (int i = 0; i < 8; ++i) k += (lab[base + i] == c);
    cntT[tid] = k;
    __syncthreads();
    int pre = 0, tot = 0;
    for (int i = 0; i < 512; ++i) {
        int v = cntT[i];
        if (i < tid) pre += v;
        tot += v;
    }
    int pos = pre;
#pragma unroll
    for (int i = 0; i < 8; ++i) {
        int n = base + i;
        if (lab[n] == c) mem[pos++] = n;
    }
    __syncthreads();

    int cnt = tot;
    size_t cbase = ((size_t)b) << 10;
    float ax = 0.f, ay = 0.f;
    const float *xr = x + ((size_t)r * NP) * SD;
    int d = tid * 2;
#pragma unroll 16
    for (int m = 0; m < cnt; ++m) {
        float2 v = *(const float2 *)(xr + ((size_t)mem[m]) * SD + d);
        ax = __fadd_rn(ax, v.x); ay = __fadd_rn(ay, v.y);
    }
    float fcnt = (float)cnt;
    float o0, o1;
    if (cnt > 0) {
        o0 = __fdiv_rn(ax, fcnt); o1 = __fdiv_rn(ay, fcnt);
    } else {
        o0 = g_centers[cbase + d + 0]; o1 = g_centers[cbase + d + 1];
    }
    g_centers[cbase + d + 0] = o0; g_centers[cbase + d + 1] = o1;
    s[d + 0] = o0; s[d + 1] = o1;
    __syncthreads();
    if (tid == 0) {
        float ss = 0.f;
#pragma unroll 8
        for (int dd = 0; dd < SD; ++dd) ss = __fadd_rn(ss, __fmul_rn(s[dd], s[dd]));
        g_c2[b] = ss;
    }
}

extern "C" void kernel_launch(void* const* d_in, const int* in_sizes, int n_in,
                              void* d_out, int out_size) {
    const float *x = (const float *)d_in[0];
    float *out = (float *)d_out;
    (void)in_sizes; (void)n_in; (void)out_size;

    init_kernel<<<RG, 1024>>>();           // launch 1
    x2_kernel<<<RG * NP / 8, 128>>>(x);    // launch 2
    gather_init_kernel<<<RG * LC, 128>>>(x);  // launch 3
    nop_kernel<<<1, 32>>>();               // launch 4 (shifts ncu onto update)
    for (int it = 0; it < 10; ++it) {
        assign_kernel<<<RG * 16, 512>>>(x, out, 0);   // launch 5, 7, ...
        update_kernel<<<RG * LC, 512>>>(x);           // launch 6 <- ncu -s5 -c1
    }
    assign_kernel<<<RG * 16, 512>>>(x, out, 1);
}